// round 1
// baseline (speedup 1.0000x reference)
#include <cuda_runtime.h>
#include <math.h>
#include <stdint.h>

// Problem dims
#define L_   12
#define D_   1024
#define NH_  16
#define HD_  64
#define HID_ 2816
#define V_   50257
#define B_   8
#define T_   1024
#define M_   (B_*T_)        // 8192 tokens

// ---------------------------------------------------------------------------
// Scratch (static device globals — no allocations allowed)
// ---------------------------------------------------------------------------
__device__ float g_x  [M_ * D_];        // residual stream
__device__ float g_h  [M_ * D_];        // layernorm output
__device__ float g_qkv[M_ * 3 * D_];    // fused qkv
__device__ float g_y  [M_ * D_];        // attention output
__device__ float g_u  [M_ * HID_];      // mlp up (silu path)
__device__ float g_g  [M_ * HID_];      // mlp gate path
__device__ float g_xf [B_ * D_];        // final-ln rows (last token per batch)

// ---------------------------------------------------------------------------
// Embedding gather: x[m, :] = wte[tokens[m], :]
// ---------------------------------------------------------------------------
__global__ void embed_k(const int* __restrict__ tok, const float* __restrict__ wte,
                        float* __restrict__ x) {
    int m = blockIdx.x;
    int t = tok[m];
    const float4* src = (const float4*)(wte + (size_t)t * D_);
    float4* dst = (float4*)(x + (size_t)m * D_);
    dst[threadIdx.x] = src[threadIdx.x];          // 256 threads * float4 = 1024
}

// ---------------------------------------------------------------------------
// LayerNorm over D=1024. One block (256 threads) per row.
// rowStride lets us reuse it for the final LN over strided last-token rows.
// ---------------------------------------------------------------------------
__global__ void ln_k(const float* __restrict__ x, const float* __restrict__ w,
                     const float* __restrict__ b, float* __restrict__ o,
                     int rowStride) {
    int row = blockIdx.x;
    int tid = threadIdx.x;
    const float* xr = x + (size_t)row * rowStride;
    float4 v = ((const float4*)xr)[tid];
    float s = v.x + v.y + v.z + v.w;
    float q = v.x*v.x + v.y*v.y + v.z*v.z + v.w*v.w;
    #pragma unroll
    for (int off = 16; off > 0; off >>= 1) {
        s += __shfl_down_sync(0xffffffffu, s, off);
        q += __shfl_down_sync(0xffffffffu, q, off);
    }
    __shared__ float ss[8], sq[8];
    int wi = tid >> 5, ln = tid & 31;
    if (ln == 0) { ss[wi] = s; sq[wi] = q; }
    __syncthreads();
    if (tid == 0) {
        float a = 0.f, c = 0.f;
        #pragma unroll
        for (int i = 0; i < 8; i++) { a += ss[i]; c += sq[i]; }
        ss[0] = a; sq[0] = c;
    }
    __syncthreads();
    float mean = ss[0] * (1.f / D_);
    float var  = sq[0] * (1.f / D_) - mean * mean;
    float rstd = rsqrtf(var + 1e-5f);
    float4 wv = ((const float4*)w)[tid];
    float4 bv = ((const float4*)b)[tid];
    float4 ov;
    ov.x = (v.x - mean) * rstd * wv.x + bv.x;
    ov.y = (v.y - mean) * rstd * wv.y + bv.y;
    ov.z = (v.z - mean) * rstd * wv.z + bv.z;
    ov.w = (v.w - mean) * rstd * wv.w + bv.w;
    ((float4*)(o + (size_t)row * D_))[tid] = ov;
}

// ---------------------------------------------------------------------------
// SGEMM "NT": C[m,n] = sum_k A[m,k] * W[n,k] (+ bias[n]) (+ C residual)
// A: MxK row-major, W: NxK row-major. M,N multiples of 128; K multiple of 8.
// Classic 128x128x8 tile, 8x8 microtile, 256 threads.
// ---------------------------------------------------------------------------
__global__ void __launch_bounds__(256)
sgemm_nt(const float* __restrict__ A, const float* __restrict__ W,
         const float* __restrict__ bias, float* __restrict__ C,
         int M, int N, int K, int residual) {
    __shared__ __align__(16) float As[8][128];
    __shared__ __align__(16) float Ws[8][128];

    const int tid = threadIdx.x;
    const int tc = tid & 15;      // 0..15 -> n microtile
    const int tr = tid >> 4;      // 0..15 -> m microtile
    const float* Ab = A + (size_t)blockIdx.y * 128 * K;
    const float* Wb = W + (size_t)blockIdx.x * 128 * K;
    const int lr = tid >> 1;           // 0..127 row
    const int lc = (tid & 1) * 4;      // 0 or 4

    float acc[8][8];
    #pragma unroll
    for (int i = 0; i < 8; i++)
        #pragma unroll
        for (int j = 0; j < 8; j++) acc[i][j] = 0.f;

    for (int k0 = 0; k0 < K; k0 += 8) {
        float4 a4 = *(const float4*)(Ab + (size_t)lr * K + k0 + lc);
        float4 w4 = *(const float4*)(Wb + (size_t)lr * K + k0 + lc);
        __syncthreads();   // prior iteration's compute finished reading smem
        As[lc + 0][lr] = a4.x; As[lc + 1][lr] = a4.y;
        As[lc + 2][lr] = a4.z; As[lc + 3][lr] = a4.w;
        Ws[lc + 0][lr] = w4.x; Ws[lc + 1][lr] = w4.y;
        Ws[lc + 2][lr] = w4.z; Ws[lc + 3][lr] = w4.w;
        __syncthreads();
        #pragma unroll
        for (int k = 0; k < 8; k++) {
            float ra[8], rw[8];
            *(float4*)(ra)     = *(const float4*)&As[k][tr * 8];
            *(float4*)(ra + 4) = *(const float4*)&As[k][tr * 8 + 4];
            *(float4*)(rw)     = *(const float4*)&Ws[k][tc * 8];
            *(float4*)(rw + 4) = *(const float4*)&Ws[k][tc * 8 + 4];
            #pragma unroll
            for (int i = 0; i < 8; i++)
                #pragma unroll
                for (int j = 0; j < 8; j++)
                    acc[i][j] = fmaf(ra[i], rw[j], acc[i][j]);
        }
    }

    const size_t mBase = (size_t)blockIdx.y * 128 + tr * 8;
    const int    nBase = blockIdx.x * 128 + tc * 8;
    #pragma unroll
    for (int i = 0; i < 8; i++) {
        float* crow = C + (mBase + i) * N + nBase;
        #pragma unroll
        for (int j = 0; j < 8; j++) {
            float v = acc[i][j];
            if (bias)     v += bias[nBase + j];
            if (residual) v += crow[j];
            crow[j] = v;
        }
    }
}

// ---------------------------------------------------------------------------
// RoPE applied in-place to q and k inside the fused qkv buffer.
// One thread per (token m, head h, rot index i in [0,32)).
// ---------------------------------------------------------------------------
__global__ void rope_k(float* __restrict__ qkv) {
    int idx = blockIdx.x * blockDim.x + threadIdx.x;  // M_*NH_*32 = 4194304
    int i = idx & 31;
    int h = (idx >> 5) & 15;
    int m = idx >> 9;
    int t = m & (T_ - 1);
    float inv = (float)pow(10000.0, -(double)i / 32.0);
    float ang = (float)t * inv;
    float sn, cs;
    sincosf(ang, &sn, &cs);
    size_t base = (size_t)m * (3 * D_) + h * 64 + i;
    float q1 = qkv[base], q2 = qkv[base + 32];
    qkv[base]        = q1 * cs - q2 * sn;
    qkv[base + 32]   = q2 * cs + q1 * sn;
    float k1 = qkv[base + 1024], k2 = qkv[base + 1056];
    qkv[base + 1024] = k1 * cs - k2 * sn;
    qkv[base + 1056] = k2 * cs + k1 * sn;
}

// ---------------------------------------------------------------------------
// Causal attention. Grid: (T/8, NH, B), 256 threads.
// Block handles 8 query rows; K/V staged through a shared 32x65 tile,
// full score rows (<=1024) kept in smem, two-pass softmax.
// ---------------------------------------------------------------------------
__global__ void __launch_bounds__(256)
attn_k(const float* __restrict__ qkv, float* __restrict__ y) {
    const int qt = blockIdx.x, h = blockIdx.y, b = blockIdx.z;
    const int q0 = qt * 8;
    const int tid = threadIdx.x;
    const int nk = q0 + 8;               // max key index + 1 for this tile
    const int nt = (nk + 31) / 32;       // 32-key tiles

    __shared__ float Qs[8][64];
    __shared__ float S[8][1024];
    __shared__ float KV[32][65];         // stride 65: conflict-free

    // Load + pre-scale Q (scale = 1/sqrt(64) = 0.125)
    if (tid < 128) {
        int qi = tid / 16, c4 = (tid % 16) * 4;
        const float* qp = qkv + (size_t)(b * T_ + q0 + qi) * (3 * D_) + h * 64 + c4;
        float4 v = *(const float4*)qp;
        Qs[qi][c4 + 0] = v.x * 0.125f; Qs[qi][c4 + 1] = v.y * 0.125f;
        Qs[qi][c4 + 2] = v.z * 0.125f; Qs[qi][c4 + 3] = v.w * 0.125f;
    }

    const int qi_ = tid >> 5;            // warp id = query row
    const int j_  = tid & 31;            // lane = key within tile / dim

    // Phase 1: scores
    for (int kt = 0; kt < nt; kt++) {
        __syncthreads();
        #pragma unroll
        for (int p = 0; p < 2; p++) {
            int idx = tid + p * 256;             // 0..511
            int r = idx >> 4, c4 = (idx & 15) * 4;
            int jg = kt * 32 + r;
            const float* kp = qkv + (size_t)(b * T_ + jg) * (3 * D_) + D_ + h * 64 + c4;
            float4 v = *(const float4*)kp;
            KV[r][c4 + 0] = v.x; KV[r][c4 + 1] = v.y;
            KV[r][c4 + 2] = v.z; KV[r][c4 + 3] = v.w;
        }
        __syncthreads();
        int jg = kt * 32 + j_;
        float s = 0.f;
        #pragma unroll
        for (int d = 0; d < 64; d++) s = fmaf(Qs[qi_][d], KV[j_][d], s);
        int qg = q0 + qi_;
        S[qi_][jg] = (jg <= qg) ? s : -1e30f;
    }
    __syncthreads();

    // Phase 2: softmax, one warp per row
    {
        int cnt = nt * 32;
        float mx = -1e30f;
        for (int j = j_; j < cnt; j += 32) mx = fmaxf(mx, S[qi_][j]);
        #pragma unroll
        for (int o = 16; o > 0; o >>= 1) mx = fmaxf(mx, __shfl_xor_sync(0xffffffffu, mx, o));
        float sum = 0.f;
        for (int j = j_; j < cnt; j += 32) {
            float e = expf(S[qi_][j] - mx);
            S[qi_][j] = e;
            sum += e;
        }
        #pragma unroll
        for (int o = 16; o > 0; o >>= 1) sum += __shfl_xor_sync(0xffffffffu, sum, o);
        float invs = 1.f / sum;
        for (int j = j_; j < cnt; j += 32) S[qi_][j] *= invs;
    }

    // Phase 3: out = P @ V
    float a0 = 0.f, a1 = 0.f;
    for (int kt = 0; kt < nt; kt++) {
        __syncthreads();
        #pragma unroll
        for (int p = 0; p < 2; p++) {
            int idx = tid + p * 256;
            int r = idx >> 4, c4 = (idx & 15) * 4;
            int jg = kt * 32 + r;
            const float* vp = qkv + (size_t)(b * T_ + jg) * (3 * D_) + 2 * D_ + h * 64 + c4;
            float4 v = *(const float4*)vp;
            KV[r][c4 + 0] = v.x; KV[r][c4 + 1] = v.y;
            KV[r][c4 + 2] = v.z; KV[r][c4 + 3] = v.w;
        }
        __syncthreads();
        #pragma unroll 8
        for (int j = 0; j < 32; j++) {
            float p = S[qi_][kt * 32 + j];
            a0 = fmaf(p, KV[j][j_],      a0);
            a1 = fmaf(p, KV[j][j_ + 32], a1);
        }
    }
    int qg = q0 + qi_;
    float* yp = y + (size_t)(b * T_ + qg) * D_ + h * 64;
    yp[j_]      = a0;
    yp[j_ + 32] = a1;
}

// ---------------------------------------------------------------------------
// u = silu(u) * g  (elementwise, vectorized)
// ---------------------------------------------------------------------------
__global__ void silumul_k(float* __restrict__ u, const float* __restrict__ g, int n4) {
    int i = blockIdx.x * blockDim.x + threadIdx.x;
    if (i < n4) {
        float4 uv = ((float4*)u)[i];
        float4 gv = ((const float4*)g)[i];
        uv.x = uv.x / (1.f + expf(-uv.x)) * gv.x;
        uv.y = uv.y / (1.f + expf(-uv.y)) * gv.y;
        uv.z = uv.z / (1.f + expf(-uv.z)) * gv.z;
        uv.w = uv.w / (1.f + expf(-uv.w)) * gv.w;
        ((float4*)u)[i] = uv;
    }
}

// ---------------------------------------------------------------------------
// Logits: out[b, n] = dot(xf[b,:], wte[n,:]); xf (8x1024) held in smem.
// ---------------------------------------------------------------------------
__global__ void __launch_bounds__(256)
logits_k(const float* __restrict__ xf, const float* __restrict__ wte,
         float* __restrict__ out) {
    __shared__ float xs[B_ * D_];       // 32 KB
    int tid = threadIdx.x;
    #pragma unroll
    for (int p = 0; p < 8; p++) {
        int i4 = tid + p * 256;
        float4 v = ((const float4*)xf)[i4];
        xs[i4 * 4 + 0] = v.x; xs[i4 * 4 + 1] = v.y;
        xs[i4 * 4 + 2] = v.z; xs[i4 * 4 + 3] = v.w;
    }
    __syncthreads();
    int n = blockIdx.x * 256 + tid;
    if (n >= V_) return;
    const float* wr = wte + (size_t)n * D_;
    float acc[8] = {0.f, 0.f, 0.f, 0.f, 0.f, 0.f, 0.f, 0.f};
    for (int k = 0; k < D_; k += 4) {
        float4 w = *(const float4*)(wr + k);
        #pragma unroll
        for (int b2 = 0; b2 < 8; b2++) {
            const float* xb = xs + b2 * D_ + k;
            acc[b2] += w.x * xb[0] + w.y * xb[1] + w.z * xb[2] + w.w * xb[3];
        }
    }
    #pragma unroll
    for (int b2 = 0; b2 < 8; b2++) out[(size_t)b2 * V_ + n] = acc[b2];
}

// ---------------------------------------------------------------------------
// Host orchestration (graph-capturable: launches only)
// ---------------------------------------------------------------------------
extern "C" void kernel_launch(void* const* d_in, const int* in_sizes, int n_in,
                              void* d_out, int out_size) {
    const int*   tokens   = (const int*)  d_in[0];
    const float* wte      = (const float*)d_in[1];
    const float* c_attn_w = (const float*)d_in[2];
    const float* c_attn_b = (const float*)d_in[3];
    const float* c_proj_w = (const float*)d_in[4];
    const float* c_proj_b = (const float*)d_in[5];
    const float* ln1_w    = (const float*)d_in[6];
    const float* ln1_b    = (const float*)d_in[7];
    const float* ln2_w    = (const float*)d_in[8];
    const float* ln2_b    = (const float*)d_in[9];
    const float* w1       = (const float*)d_in[10];
    const float* w3       = (const float*)d_in[11];
    const float* w2       = (const float*)d_in[12];
    const float* lnf_w    = (const float*)d_in[13];
    const float* lnf_b    = (const float*)d_in[14];
    float* out = (float*)d_out;

    float *x, *h, *qkv, *y, *u, *g, *xf;
    cudaGetSymbolAddress((void**)&x,   g_x);
    cudaGetSymbolAddress((void**)&h,   g_h);
    cudaGetSymbolAddress((void**)&qkv, g_qkv);
    cudaGetSymbolAddress((void**)&y,   g_y);
    cudaGetSymbolAddress((void**)&u,   g_u);
    cudaGetSymbolAddress((void**)&g,   g_g);
    cudaGetSymbolAddress((void**)&xf,  g_xf);

    embed_k<<<M_, 256>>>(tokens, wte, x);

    for (int l = 0; l < L_; l++) {
        // ln1
        ln_k<<<M_, 256>>>(x, ln1_w + l * D_, ln1_b + l * D_, h, D_);
        // qkv = h @ c_attn_w^T + c_attn_b
        sgemm_nt<<<dim3(3 * D_ / 128, M_ / 128), 256>>>(
            h, c_attn_w + (size_t)l * 3 * D_ * D_, c_attn_b + l * 3 * D_,
            qkv, M_, 3 * D_, D_, 0);
        // rope on q,k
        rope_k<<<(M_ * NH_ * 32) / 256, 256>>>(qkv);
        // attention -> y
        attn_k<<<dim3(T_ / 8, NH_, B_), 256>>>(qkv, y);
        // x += y @ c_proj_w^T + c_proj_b
        sgemm_nt<<<dim3(D_ / 128, M_ / 128), 256>>>(
            y, c_proj_w + (size_t)l * D_ * D_, c_proj_b + l * D_,
            x, M_, D_, D_, 1);
        // ln2
        ln_k<<<M_, 256>>>(x, ln2_w + l * D_, ln2_b + l * D_, h, D_);
        // u = h @ w1^T ; g = h @ w3^T
        sgemm_nt<<<dim3(HID_ / 128, M_ / 128), 256>>>(
            h, w1 + (size_t)l * HID_ * D_, nullptr, u, M_, HID_, D_, 0);
        sgemm_nt<<<dim3(HID_ / 128, M_ / 128), 256>>>(
            h, w3 + (size_t)l * HID_ * D_, nullptr, g, M_, HID_, D_, 0);
        // u = silu(u) * g
        silumul_k<<<(M_ * HID_ / 4 + 255) / 256, 256>>>(u, g, M_ * HID_ / 4);
        // x += u @ w2^T
        sgemm_nt<<<dim3(D_ / 128, M_ / 128), 256>>>(
            u, w2 + (size_t)l * D_ * HID_, nullptr, x, M_, D_, HID_, 1);
    }

    // final LN on last-token rows only, then logits
    ln_k<<<B_, 256>>>(x + (size_t)(T_ - 1) * D_, lnf_w, lnf_b, xf, T_ * D_);
    logits_k<<<(V_ + 255) / 256, 256>>>(xf, wte, out);
}